// round 14
// baseline (speedup 1.0000x reference)
#include <cuda_runtime.h>
#include <cuda_fp16.h>
#include <math.h>

#define MAXN 100000
#define DIM  256

// Scratch (device globals; allocation-free)
__device__ __half2 g_Xh[(size_t)MAXN * (DIM / 2)];    // fp16 copy of right_embed
__device__ __half2 g_W1h[DIM * (DIM / 2)];
__device__ __half2 g_Wrh[DIM * (DIM / 2)];
__device__ __half2 g_Hh[(size_t)MAXN * (DIM / 2)];    // H = X@W1, fp16
__device__ __half2 g_AGGh[(size_t)MAXN * (DIM / 2)];  // relu(segment_sum), fp16
__device__ int     g_rowptr[MAXN + 1];

// ---------------------------------------------------------------------------
// helpers
// ---------------------------------------------------------------------------
__device__ __forceinline__ unsigned smem_u32(const void* p) {
    return (unsigned)__cvta_generic_to_shared(p);
}
__device__ __forceinline__ void ldsm4(unsigned* r, unsigned addr) {
    asm volatile("ldmatrix.sync.aligned.m8n8.x4.shared.b16 {%0,%1,%2,%3}, [%4];"
                 : "=r"(r[0]), "=r"(r[1]), "=r"(r[2]), "=r"(r[3]) : "r"(addr));
}
__device__ __forceinline__ void ldsm4t(unsigned* r, unsigned addr) {
    asm volatile("ldmatrix.sync.aligned.m8n8.x4.trans.shared.b16 {%0,%1,%2,%3}, [%4];"
                 : "=r"(r[0]), "=r"(r[1]), "=r"(r[2]), "=r"(r[3]) : "r"(addr));
}
__device__ __forceinline__ void mma_f16(float* c, const unsigned* a, const unsigned* b) {
    asm volatile(
        "mma.sync.aligned.m16n8k16.row.col.f32.f16.f16.f32 "
        "{%0,%1,%2,%3}, {%4,%5,%6,%7}, {%8,%9}, {%0,%1,%2,%3};\n"
        : "+f"(c[0]), "+f"(c[1]), "+f"(c[2]), "+f"(c[3])
        : "r"(a[0]), "r"(a[1]), "r"(a[2]), "r"(a[3]), "r"(b[0]), "r"(b[1]));
}
__device__ __forceinline__ void cp16(void* dst, const void* src) {
    unsigned d = smem_u32(dst);
    asm volatile("cp.async.cg.shared.global [%0], [%1], 16;\n" :: "r"(d), "l"(src));
}
#define CP_COMMIT() asm volatile("cp.async.commit_group;\n" ::: "memory")
#define CP_WAIT(n)  asm volatile("cp.async.wait_group %0;\n" :: "n"(n) : "memory")

__device__ __forceinline__ uint2 f4toh4(float4 v) {
    __half2 h0 = __floats2half2_rn(v.x, v.y);
    __half2 h1 = __floats2half2_rn(v.z, v.w);
    uint2 u;
    u.x = *(unsigned*)&h0;
    u.y = *(unsigned*)&h1;
    return u;
}

// ---------------------------------------------------------------------------
// Kernel 0a: X fp32 -> fp16
// ---------------------------------------------------------------------------
__global__ void convert_x(const float* __restrict__ src, int n4) {
    int i = blockIdx.x * blockDim.x + threadIdx.x;
    if (i >= n4) return;
    float4 v = *(const float4*)(src + (size_t)i * 4);
    *(uint2*)(g_Xh + (size_t)i * 2) = f4toh4(v);
}

// Kernel 0b: both weight matrices in one launch
__global__ void convert_w(const float* __restrict__ W1, const float* __restrict__ Wr) {
    const int w4 = DIM * (DIM / 4);
    int i = blockIdx.x * blockDim.x + threadIdx.x;
    if (i < w4) {
        float4 v = *(const float4*)(W1 + (size_t)i * 4);
        *(uint2*)(g_W1h + (size_t)i * 2) = f4toh4(v);
    } else if (i < 2 * w4) {
        int j = i - w4;
        float4 v = *(const float4*)(Wr + (size_t)j * 4);
        *(uint2*)(g_Wrh + (size_t)j * 2) = f4toh4(v);
    }
}

// ---------------------------------------------------------------------------
// Kernel 1: row_ptr via boundary scatter over sorted edge_rows
// ---------------------------------------------------------------------------
__global__ void build_rowptr_fast(const int* __restrict__ rows, int E, int Nn) {
    int i = blockIdx.x * blockDim.x + threadIdx.x;
    if (i >= E) return;
    int r = rows[i];
    if (i == 0) {
        for (int q = 0; q <= r; q++) g_rowptr[q] = 0;
    } else {
        int rp = rows[i - 1];
        for (int q = rp + 1; q <= r; q++) g_rowptr[q] = i;
    }
    if (i == E - 1) {
        for (int q = r + 1; q <= Nn; q++) g_rowptr[q] = E;
    }
}

// ---------------------------------------------------------------------------
// GEMM config: fp16 mma m16n8k16. BM=128, BN=128, BK=32.
// 256 threads = 8 warps (4m x 2n), warp tile 32x64 = 2(m16) x 8(n8).
// 2-stage cp.async double buffer in STATIC smem. launch_bounds(256,3) to
// force <=85 regs -> 3 blocks/SM (occ 37.5% vs 25%).
// ---------------------------------------------------------------------------
#define BM 128
#define BN 128
#define BK 32
#define A_LDH 40
#define B_LDH 136
#define KITERS (DIM / BK)   // 8

#define GEMM_ISSUE_STAGE(s, k0)                                                 \
    {                                                                           \
        cp16(&As[s][arow][acol0], Agp + k0);                                    \
        cp16(&As[s][arow][acol0 + 8], Agp + k0 + 8);                            \
        cp16(&Bs[s][brow][bcol], Bgp + (size_t)k0 * DIM);                       \
        cp16(&Bs[s][brow + 16][bcol], Bgp + (size_t)(k0 + 16) * DIM);           \
        CP_COMMIT();                                                            \
    }

#define GEMM_CORE_COMPUTE(s)                                                    \
    _Pragma("unroll")                                                           \
    for (int kk = 0; kk < BK; kk += 16) {                                       \
        unsigned a[2][4], b[4][4];                                              \
        _Pragma("unroll")                                                       \
        for (int mi = 0; mi < 2; mi++) {                                        \
            int m0 = wm * 32 + mi * 16;                                         \
            unsigned ad = smem_u32(                                             \
                &As[s][m0 + (lane & 7) + ((lane >> 3) & 1) * 8]                 \
                     [kk + (lane >> 4) * 8]);                                   \
            ldsm4(a[mi], ad);                                                   \
        }                                                                       \
        _Pragma("unroll")                                                       \
        for (int g = 0; g < 4; g++) {                                           \
            int nb = wn * 64 + g * 16;                                          \
            unsigned bd = smem_u32(                                             \
                &Bs[s][kk + (lane & 7) + ((lane >> 3) & 1) * 8]                 \
                     [nb + (lane >> 4) * 8]);                                   \
            ldsm4t(b[g], bd);                                                   \
        }                                                                       \
        _Pragma("unroll")                                                       \
        for (int mi = 0; mi < 2; mi++)                                          \
            _Pragma("unroll")                                                   \
            for (int nj = 0; nj < 8; nj++)                                      \
                mma_f16(c[mi][nj], a[mi], &b[nj >> 1][(nj & 1) * 2]);           \
    }

#define GEMM_PIPELINE_BODY                                                      \
    GEMM_ISSUE_STAGE(0, 0);                                                     \
    GEMM_ISSUE_STAGE(1, BK);                                                    \
    _Pragma("unroll 1")                                                         \
    for (int it = 0; it < KITERS; it++) {                                       \
        if (it + 1 < KITERS) { CP_WAIT(1); } else { CP_WAIT(0); }               \
        __syncthreads();                                                        \
        GEMM_CORE_COMPUTE(it & 1);                                              \
        __syncthreads();                                                        \
        if (it + 2 < KITERS) GEMM_ISSUE_STAGE(it & 1, (it + 2) * BK);           \
    }

// ---------------------------------------------------------------------------
// Kernel 2: H(fp16) = Xh @ W1h
// ---------------------------------------------------------------------------
__global__ __launch_bounds__(256, 3)
void gemm_h(int M) {
    __shared__ __align__(16) __half As[2][BM][A_LDH];
    __shared__ __align__(16) __half Bs[2][BK][B_LDH];

    const int t = threadIdx.x;
    const int lane = t & 31;
    const int wid = t >> 5;
    const int wm = wid & 3;
    const int wn = wid >> 2;
    const int grp = lane >> 2;
    const int tig = lane & 3;
    const int n0 = blockIdx.x * BN;
    const int row0 = blockIdx.y * BM;

    const int arow = t >> 1;
    const int acol0 = (t & 1) * 16;
    const int brow = t >> 4;
    const int bcol = (t & 15) * 8;

    const __half* Agp = (const __half*)g_Xh + (size_t)min(row0 + arow, M - 1) * DIM + acol0;
    const __half* Bgp = (const __half*)g_W1h + (size_t)brow * DIM + n0 + bcol;

    float c[2][8][4];
#pragma unroll
    for (int mi = 0; mi < 2; mi++)
#pragma unroll
        for (int nj = 0; nj < 8; nj++)
#pragma unroll
            for (int q = 0; q < 4; q++) c[mi][nj][q] = 0.f;

    GEMM_PIPELINE_BODY;

#pragma unroll
    for (int mi = 0; mi < 2; mi++) {
#pragma unroll
        for (int nj = 0; nj < 8; nj++) {
            int r = row0 + wm * 32 + mi * 16 + grp;
            int col = n0 + wn * 64 + nj * 8 + tig * 2;
            if (r < M)
                g_Hh[(size_t)r * 128 + (col >> 1)] = __floats2half2_rn(c[mi][nj][0], c[mi][nj][1]);
            if (r + 8 < M)
                g_Hh[(size_t)(r + 8) * 128 + (col >> 1)] = __floats2half2_rn(c[mi][nj][2], c[mi][nj][3]);
        }
    }
}

// ---------------------------------------------------------------------------
// Kernel 3: SpMM + ReLU, warp per row, unroll-8 main loop (MLP 8).
// Edge arrays are one-shot -> streaming loads (keep H resident in L2).
// ---------------------------------------------------------------------------
__device__ __forceinline__ void spmm_accum(float4 p, float v, float* acc) {
    const __half2* h = (const __half2*)&p;
#pragma unroll
    for (int k = 0; k < 4; k++) {
        float2 f = __half22float2(h[k]);
        acc[2 * k]     = fmaf(v, f.x, acc[2 * k]);
        acc[2 * k + 1] = fmaf(v, f.y, acc[2 * k + 1]);
    }
}

__global__ __launch_bounds__(256)
void spmm_relu(const float* __restrict__ ev, const int* __restrict__ ec, int Nrows) {
    int r = blockIdx.x * 8 + (threadIdx.x >> 5);
    if (r >= Nrows) return;
    const int lane = threadIdx.x & 31;
    const int s = __ldg(g_rowptr + r);
    const int e = __ldg(g_rowptr + r + 1);
    const float4* H4 = (const float4*)g_Hh;

    float acc[8];
#pragma unroll
    for (int k = 0; k < 8; k++) acc[k] = 0.f;

    int i = s;
    for (; i + 8 <= e; i += 8) {
        int   cc[8];
        float vv[8];
        float4 pp[8];
#pragma unroll
        for (int u = 0; u < 8; u++) cc[u] = __ldcs(ec + i + u);
#pragma unroll
        for (int u = 0; u < 8; u++) vv[u] = __ldcs(ev + i + u);
#pragma unroll
        for (int u = 0; u < 8; u++) pp[u] = H4[(size_t)cc[u] * 32 + lane];
#pragma unroll
        for (int u = 0; u < 8; u++) spmm_accum(pp[u], vv[u], acc);
    }
    if (i + 4 <= e) {
        int   cc[4];
        float vv[4];
        float4 pp[4];
#pragma unroll
        for (int u = 0; u < 4; u++) cc[u] = __ldcs(ec + i + u);
#pragma unroll
        for (int u = 0; u < 4; u++) vv[u] = __ldcs(ev + i + u);
#pragma unroll
        for (int u = 0; u < 4; u++) pp[u] = H4[(size_t)cc[u] * 32 + lane];
#pragma unroll
        for (int u = 0; u < 4; u++) spmm_accum(pp[u], vv[u], acc);
        i += 4;
    }
    for (; i < e; i++) {
        int c0 = __ldcs(ec + i);
        float v0 = __ldcs(ev + i);
        float4 p0 = H4[(size_t)c0 * 32 + lane];
        spmm_accum(p0, v0, acc);
    }

    __half2 o[4];
#pragma unroll
    for (int k = 0; k < 4; k++)
        o[k] = __floats2half2_rn(fmaxf(acc[2 * k], 0.f), fmaxf(acc[2 * k + 1], 0.f));
    ((float4*)g_AGGh)[(size_t)r * 32 + lane] = *(float4*)o;
}

// ---------------------------------------------------------------------------
// Kernel 4: gate = sigmoid(Xh[perm] @ Wrh + br); out = gate*AGG + (1-gate)*Xh[perm]
// ---------------------------------------------------------------------------
__global__ __launch_bounds__(256, 3)
void gemm_gate(const float* __restrict__ brv, const int* __restrict__ perm,
               float* __restrict__ out, int M) {
    __shared__ __align__(16) __half As[2][BM][A_LDH];
    __shared__ __align__(16) __half Bs[2][BK][B_LDH];
    __shared__ int pm_s[BM];

    const int t = threadIdx.x;
    const int lane = t & 31;
    const int wid = t >> 5;
    const int wm = wid & 3;
    const int wn = wid >> 2;
    const int grp = lane >> 2;
    const int tig = lane & 3;
    const int n0 = blockIdx.x * BN;
    const int row0 = blockIdx.y * BM;

    if (t < BM) pm_s[t] = perm[min(row0 + t, M - 1)];
    __syncthreads();

    const int arow = t >> 1;
    const int acol0 = (t & 1) * 16;
    const int brow = t >> 4;
    const int bcol = (t & 15) * 8;

    const __half* Agp = (const __half*)g_Xh + (size_t)pm_s[arow] * DIM + acol0;
    const __half* Bgp = (const __half*)g_Wrh + (size_t)brow * DIM + n0 + bcol;

    float c[2][8][4];
#pragma unroll
    for (int mi = 0; mi < 2; mi++)
#pragma unroll
        for (int nj = 0; nj < 8; nj++)
#pragma unroll
            for (int q = 0; q < 4; q++) c[mi][nj][q] = 0.f;

    GEMM_PIPELINE_BODY;

#pragma unroll
    for (int mi = 0; mi < 2; mi++) {
#pragma unroll
        for (int nj = 0; nj < 8; nj++) {
            int lr = wm * 32 + mi * 16 + grp;
            int col = n0 + wn * 64 + nj * 8 + tig * 2;
            float b0 = brv[col], b1 = brv[col + 1];
#pragma unroll
            for (int half = 0; half < 2; half++) {
                int m = row0 + lr + half * 8;
                if (m >= M) continue;
                int pr = pm_s[lr + half * 8];
                float2 l = __half22float2(g_Xh[(size_t)pr * 128 + (col >> 1)]);
                float2 a = __half22float2(g_AGGh[(size_t)m * 128 + (col >> 1)]);
                float x0 = c[mi][nj][half * 2 + 0] + b0;
                float x1 = c[mi][nj][half * 2 + 1] + b1;
                float g0 = 1.0f / (1.0f + expf(-x0));
                float g1 = 1.0f / (1.0f + expf(-x1));
                float2 o;
                o.x = g0 * a.x + (1.0f - g0) * l.x;
                o.y = g1 * a.y + (1.0f - g1) * l.y;
                *(float2*)(out + (size_t)m * DIM + col) = o;
            }
        }
    }
}

// ---------------------------------------------------------------------------
// Launch
// ---------------------------------------------------------------------------
extern "C" void kernel_launch(void* const* d_in, const int* in_sizes, int n_in,
                              void* d_out, int out_size) {
    const float* right_embed = (const float*)d_in[0];
    const float* W1          = (const float*)d_in[1];
    const float* Wr          = (const float*)d_in[2];
    const float* br          = (const float*)d_in[3];
    const float* edge_vals   = (const float*)d_in[4];
    const int*   edge_rows   = (const int*)d_in[5];
    const int*   edge_cols   = (const int*)d_in[6];
    const int*   perm        = (const int*)d_in[7];

    const int E = in_sizes[4];
    const int N = in_sizes[7];
    float* out = (float*)d_out;

    // 0. fp16 conversions
    {
        int n4 = N * (DIM / 4);
        convert_x<<<(n4 + 255) / 256, 256>>>(right_embed, n4);
        int w2 = 2 * DIM * (DIM / 4);
        convert_w<<<(w2 + 255) / 256, 256>>>(W1, Wr);
    }
    // 1. CSR row pointers (boundary scatter)
    {
        build_rowptr_fast<<<(E + 255) / 256, 256>>>(edge_rows, E, N);
    }
    // 2. H = Xh @ W1h
    {
        dim3 grid(DIM / BN, (N + BM - 1) / BM);
        gemm_h<<<grid, 256>>>(N);
    }
    // 3. SpMM + ReLU
    {
        spmm_relu<<<(N + 7) / 8, 256>>>(edge_vals, edge_cols, N);
    }
    // 4. gate blend
    {
        dim3 grid(DIM / BN, (N + BM - 1) / BM);
        gemm_gate<<<grid, 256>>>(br, perm, out, N);
    }
}

// round 15
// speedup vs baseline: 1.0232x; 1.0232x over previous
#include <cuda_runtime.h>
#include <cuda_fp16.h>
#include <math.h>

#define MAXN 100000
#define DIM  256

// Scratch (device globals; allocation-free)
__device__ __half2 g_Xh[(size_t)MAXN * (DIM / 2)];    // fp16 copy of right_embed
__device__ __half2 g_W1h[DIM * (DIM / 2)];
__device__ __half2 g_Wrh[DIM * (DIM / 2)];
__device__ __half2 g_Hh[(size_t)MAXN * (DIM / 2)];    // H = X@W1, fp16
__device__ __half2 g_AGGh[(size_t)MAXN * (DIM / 2)];  // relu(segment_sum), fp16
__device__ int     g_rowptr[MAXN + 1];

// ---------------------------------------------------------------------------
// helpers
// ---------------------------------------------------------------------------
__device__ __forceinline__ unsigned smem_u32(const void* p) {
    return (unsigned)__cvta_generic_to_shared(p);
}
__device__ __forceinline__ void ldsm4(unsigned* r, unsigned addr) {
    asm volatile("ldmatrix.sync.aligned.m8n8.x4.shared.b16 {%0,%1,%2,%3}, [%4];"
                 : "=r"(r[0]), "=r"(r[1]), "=r"(r[2]), "=r"(r[3]) : "r"(addr));
}
__device__ __forceinline__ void ldsm4t(unsigned* r, unsigned addr) {
    asm volatile("ldmatrix.sync.aligned.m8n8.x4.trans.shared.b16 {%0,%1,%2,%3}, [%4];"
                 : "=r"(r[0]), "=r"(r[1]), "=r"(r[2]), "=r"(r[3]) : "r"(addr));
}
__device__ __forceinline__ void mma_f16(float* c, const unsigned* a, const unsigned* b) {
    asm volatile(
        "mma.sync.aligned.m16n8k16.row.col.f32.f16.f16.f32 "
        "{%0,%1,%2,%3}, {%4,%5,%6,%7}, {%8,%9}, {%0,%1,%2,%3};\n"
        : "+f"(c[0]), "+f"(c[1]), "+f"(c[2]), "+f"(c[3])
        : "r"(a[0]), "r"(a[1]), "r"(a[2]), "r"(a[3]), "r"(b[0]), "r"(b[1]));
}
__device__ __forceinline__ void cp16(void* dst, const void* src) {
    unsigned d = smem_u32(dst);
    asm volatile("cp.async.cg.shared.global [%0], [%1], 16;\n" :: "r"(d), "l"(src));
}
#define CP_COMMIT() asm volatile("cp.async.commit_group;\n" ::: "memory")
#define CP_WAIT(n)  asm volatile("cp.async.wait_group %0;\n" :: "n"(n) : "memory")

__device__ __forceinline__ uint2 f4toh4(float4 v) {
    __half2 h0 = __floats2half2_rn(v.x, v.y);
    __half2 h1 = __floats2half2_rn(v.z, v.w);
    uint2 u;
    u.x = *(unsigned*)&h0;
    u.y = *(unsigned*)&h1;
    return u;
}

// ---------------------------------------------------------------------------
// Kernel 0a: X fp32 -> fp16
// ---------------------------------------------------------------------------
__global__ void convert_x(const float* __restrict__ src, int n4) {
    int i = blockIdx.x * blockDim.x + threadIdx.x;
    if (i >= n4) return;
    float4 v = *(const float4*)(src + (size_t)i * 4);
    *(uint2*)(g_Xh + (size_t)i * 2) = f4toh4(v);
}

// Kernel 0b: both weight matrices in one launch
__global__ void convert_w(const float* __restrict__ W1, const float* __restrict__ Wr) {
    const int w4 = DIM * (DIM / 4);
    int i = blockIdx.x * blockDim.x + threadIdx.x;
    if (i < w4) {
        float4 v = *(const float4*)(W1 + (size_t)i * 4);
        *(uint2*)(g_W1h + (size_t)i * 2) = f4toh4(v);
    } else if (i < 2 * w4) {
        int j = i - w4;
        float4 v = *(const float4*)(Wr + (size_t)j * 4);
        *(uint2*)(g_Wrh + (size_t)j * 2) = f4toh4(v);
    }
}

// ---------------------------------------------------------------------------
// Kernel 1: row_ptr via boundary scatter over sorted edge_rows
// ---------------------------------------------------------------------------
__global__ void build_rowptr_fast(const int* __restrict__ rows, int E, int Nn) {
    int i = blockIdx.x * blockDim.x + threadIdx.x;
    if (i >= E) return;
    int r = rows[i];
    if (i == 0) {
        for (int q = 0; q <= r; q++) g_rowptr[q] = 0;
    } else {
        int rp = rows[i - 1];
        for (int q = rp + 1; q <= r; q++) g_rowptr[q] = i;
    }
    if (i == E - 1) {
        for (int q = r + 1; q <= Nn; q++) g_rowptr[q] = E;
    }
}

// ---------------------------------------------------------------------------
// GEMM config: fp16 mma m16n8k16. BM=128, BN=128, BK=32.
// 256 threads = 8 warps (4m x 2n), warp tile 32x64 = 2(m16) x 8(n8).
// 3-stage cp.async pipeline, ONE __syncthreads per iteration:
// at iter 'it' we issue into stage (it+2)%3 == (it-1)%3, whose readers all
// passed this iteration's top barrier (CUTLASS multistage invariant).
// 56.8KB dynamic smem.
// ---------------------------------------------------------------------------
#define BM 128
#define BN 128
#define BK 32
#define A_LDH 40
#define B_LDH 136
#define STAGES 3
#define KITERS (DIM / BK)   // 8
#define A_STAGE_H (BM * A_LDH)   // 5120 halves
#define B_STAGE_H (BK * B_LDH)   // 4352 halves
#define SMEM_BYTES (STAGES * (A_STAGE_H + B_STAGE_H) * 2)   // 56832

#define GEMM_ISSUE_STAGE(s, k0)                                                 \
    {                                                                           \
        cp16(&As[s][arow][acol0], Agp + k0);                                    \
        cp16(&As[s][arow][acol0 + 8], Agp + k0 + 8);                            \
        cp16(&Bs[s][brow][bcol], Bgp + (size_t)k0 * DIM);                       \
        cp16(&Bs[s][brow + 16][bcol], Bgp + (size_t)(k0 + 16) * DIM);           \
        CP_COMMIT();                                                            \
    }

#define GEMM_CORE_COMPUTE(s)                                                    \
    _Pragma("unroll")                                                           \
    for (int kk = 0; kk < BK; kk += 16) {                                       \
        unsigned a[2][4], b[4][4];                                              \
        _Pragma("unroll")                                                       \
        for (int mi = 0; mi < 2; mi++) {                                        \
            int m0 = wm * 32 + mi * 16;                                         \
            unsigned ad = smem_u32(                                             \
                &As[s][m0 + (lane & 7) + ((lane >> 3) & 1) * 8]                 \
                     [kk + (lane >> 4) * 8]);                                   \
            ldsm4(a[mi], ad);                                                   \
        }                                                                       \
        _Pragma("unroll")                                                       \
        for (int g = 0; g < 4; g++) {                                           \
            int nb = wn * 64 + g * 16;                                          \
            unsigned bd = smem_u32(                                             \
                &Bs[s][kk + (lane & 7) + ((lane >> 3) & 1) * 8]                 \
                     [nb + (lane >> 4) * 8]);                                   \
            ldsm4t(b[g], bd);                                                   \
        }                                                                       \
        _Pragma("unroll")                                                       \
        for (int mi = 0; mi < 2; mi++)                                          \
            _Pragma("unroll")                                                   \
            for (int nj = 0; nj < 8; nj++)                                      \
                mma_f16(c[mi][nj], a[mi], &b[nj >> 1][(nj & 1) * 2]);           \
    }

// One barrier per iteration. Wait: group 'it' must be complete before compute;
// pending groups at top of iter it is <=2 (steady) -> wait(1); last -> wait(0).
#define GEMM_PIPELINE_BODY                                                      \
    GEMM_ISSUE_STAGE(0, 0);                                                     \
    GEMM_ISSUE_STAGE(1, BK);                                                    \
    _Pragma("unroll 1")                                                         \
    for (int it = 0; it < KITERS; it++) {                                       \
        if (it + 1 < KITERS) { CP_WAIT(1); } else { CP_WAIT(0); }               \
        __syncthreads();                                                        \
        GEMM_CORE_COMPUTE(it % STAGES);                                         \
        if (it + 2 < KITERS)                                                    \
            GEMM_ISSUE_STAGE((it + 2) % STAGES, (it + 2) * BK);                 \
    }

// ---------------------------------------------------------------------------
// Kernel 2: H(fp16) = Xh @ W1h
// ---------------------------------------------------------------------------
__global__ __launch_bounds__(256)
void gemm_h(int M) {
    extern __shared__ __align__(16) char smem_raw[];
    __half (*As)[BM][A_LDH] = (__half(*)[BM][A_LDH])smem_raw;
    __half (*Bs)[BK][B_LDH] = (__half(*)[BK][B_LDH])(smem_raw + STAGES * A_STAGE_H * 2);

    const int t = threadIdx.x;
    const int lane = t & 31;
    const int wid = t >> 5;
    const int wm = wid & 3;
    const int wn = wid >> 2;
    const int grp = lane >> 2;
    const int tig = lane & 3;
    const int n0 = blockIdx.x * BN;
    const int row0 = blockIdx.y * BM;

    const int arow = t >> 1;
    const int acol0 = (t & 1) * 16;
    const int brow = t >> 4;
    const int bcol = (t & 15) * 8;

    const __half* Agp = (const __half*)g_Xh + (size_t)min(row0 + arow, M - 1) * DIM + acol0;
    const __half* Bgp = (const __half*)g_W1h + (size_t)brow * DIM + n0 + bcol;

    float c[2][8][4];
#pragma unroll
    for (int mi = 0; mi < 2; mi++)
#pragma unroll
        for (int nj = 0; nj < 8; nj++)
#pragma unroll
            for (int q = 0; q < 4; q++) c[mi][nj][q] = 0.f;

    GEMM_PIPELINE_BODY;

#pragma unroll
    for (int mi = 0; mi < 2; mi++) {
#pragma unroll
        for (int nj = 0; nj < 8; nj++) {
            int r = row0 + wm * 32 + mi * 16 + grp;
            int col = n0 + wn * 64 + nj * 8 + tig * 2;
            if (r < M)
                g_Hh[(size_t)r * 128 + (col >> 1)] = __floats2half2_rn(c[mi][nj][0], c[mi][nj][1]);
            if (r + 8 < M)
                g_Hh[(size_t)(r + 8) * 128 + (col >> 1)] = __floats2half2_rn(c[mi][nj][2], c[mi][nj][3]);
        }
    }
}

// ---------------------------------------------------------------------------
// Kernel 3: SpMM + ReLU, warp per row, unroll-8 main loop (MLP 8).
// Edge arrays are one-shot -> streaming loads (keep H resident in L2).
// ---------------------------------------------------------------------------
__device__ __forceinline__ void spmm_accum(float4 p, float v, float* acc) {
    const __half2* h = (const __half2*)&p;
#pragma unroll
    for (int k = 0; k < 4; k++) {
        float2 f = __half22float2(h[k]);
        acc[2 * k]     = fmaf(v, f.x, acc[2 * k]);
        acc[2 * k + 1] = fmaf(v, f.y, acc[2 * k + 1]);
    }
}

__global__ __launch_bounds__(256)
void spmm_relu(const float* __restrict__ ev, const int* __restrict__ ec, int Nrows) {
    int r = blockIdx.x * 8 + (threadIdx.x >> 5);
    if (r >= Nrows) return;
    const int lane = threadIdx.x & 31;
    const int s = __ldg(g_rowptr + r);
    const int e = __ldg(g_rowptr + r + 1);
    const float4* H4 = (const float4*)g_Hh;

    float acc[8];
#pragma unroll
    for (int k = 0; k < 8; k++) acc[k] = 0.f;

    int i = s;
    for (; i + 8 <= e; i += 8) {
        int   cc[8];
        float vv[8];
        float4 pp[8];
#pragma unroll
        for (int u = 0; u < 8; u++) cc[u] = __ldcs(ec + i + u);
#pragma unroll
        for (int u = 0; u < 8; u++) vv[u] = __ldcs(ev + i + u);
#pragma unroll
        for (int u = 0; u < 8; u++) pp[u] = H4[(size_t)cc[u] * 32 + lane];
#pragma unroll
        for (int u = 0; u < 8; u++) spmm_accum(pp[u], vv[u], acc);
    }
    if (i + 4 <= e) {
        int   cc[4];
        float vv[4];
        float4 pp[4];
#pragma unroll
        for (int u = 0; u < 4; u++) cc[u] = __ldcs(ec + i + u);
#pragma unroll
        for (int u = 0; u < 4; u++) vv[u] = __ldcs(ev + i + u);
#pragma unroll
        for (int u = 0; u < 4; u++) pp[u] = H4[(size_t)cc[u] * 32 + lane];
#pragma unroll
        for (int u = 0; u < 4; u++) spmm_accum(pp[u], vv[u], acc);
        i += 4;
    }
    for (; i < e; i++) {
        int c0 = __ldcs(ec + i);
        float v0 = __ldcs(ev + i);
        float4 p0 = H4[(size_t)c0 * 32 + lane];
        spmm_accum(p0, v0, acc);
    }

    __half2 o[4];
#pragma unroll
    for (int k = 0; k < 4; k++)
        o[k] = __floats2half2_rn(fmaxf(acc[2 * k], 0.f), fmaxf(acc[2 * k + 1], 0.f));
    ((float4*)g_AGGh)[(size_t)r * 32 + lane] = *(float4*)o;
}

// ---------------------------------------------------------------------------
// Kernel 4: gate = sigmoid(Xh[perm] @ Wrh + br); out = gate*AGG + (1-gate)*Xh[perm]
// ---------------------------------------------------------------------------
__global__ __launch_bounds__(256)
void gemm_gate(const float* __restrict__ brv, const int* __restrict__ perm,
               float* __restrict__ out, int M) {
    extern __shared__ __align__(16) char smem_raw[];
    __half (*As)[BM][A_LDH] = (__half(*)[BM][A_LDH])smem_raw;
    __half (*Bs)[BK][B_LDH] = (__half(*)[BK][B_LDH])(smem_raw + STAGES * A_STAGE_H * 2);
    __shared__ int pm_s[BM];

    const int t = threadIdx.x;
    const int lane = t & 31;
    const int wid = t >> 5;
    const int wm = wid & 3;
    const int wn = wid >> 2;
    const int grp = lane >> 2;
    const int tig = lane & 3;
    const int n0 = blockIdx.x * BN;
    const int row0 = blockIdx.y * BM;

    if (t < BM) pm_s[t] = perm[min(row0 + t, M - 1)];
    __syncthreads();

    const int arow = t >> 1;
    const int acol0 = (t & 1) * 16;
    const int brow = t >> 4;
    const int bcol = (t & 15) * 8;

    const __half* Agp = (const __half*)g_Xh + (size_t)pm_s[arow] * DIM + acol0;
    const __half* Bgp = (const __half*)g_Wrh + (size_t)brow * DIM + n0 + bcol;

    float c[2][8][4];
#pragma unroll
    for (int mi = 0; mi < 2; mi++)
#pragma unroll
        for (int nj = 0; nj < 8; nj++)
#pragma unroll
            for (int q = 0; q < 4; q++) c[mi][nj][q] = 0.f;

    GEMM_PIPELINE_BODY;

#pragma unroll
    for (int mi = 0; mi < 2; mi++) {
#pragma unroll
        for (int nj = 0; nj < 8; nj++) {
            int lr = wm * 32 + mi * 16 + grp;
            int col = n0 + wn * 64 + nj * 8 + tig * 2;
            float b0 = brv[col], b1 = brv[col + 1];
#pragma unroll
            for (int half = 0; half < 2; half++) {
                int m = row0 + lr + half * 8;
                if (m >= M) continue;
                int pr = pm_s[lr + half * 8];
                float2 l = __half22float2(g_Xh[(size_t)pr * 128 + (col >> 1)]);
                float2 a = __half22float2(g_AGGh[(size_t)m * 128 + (col >> 1)]);
                float x0 = c[mi][nj][half * 2 + 0] + b0;
                float x1 = c[mi][nj][half * 2 + 1] + b1;
                float g0 = 1.0f / (1.0f + expf(-x0));
                float g1 = 1.0f / (1.0f + expf(-x1));
                float2 o;
                o.x = g0 * a.x + (1.0f - g0) * l.x;
                o.y = g1 * a.y + (1.0f - g1) * l.y;
                *(float2*)(out + (size_t)m * DIM + col) = o;
            }
        }
    }
}

// ---------------------------------------------------------------------------
// Launch (attribute set unconditionally each call; deterministic, no allocs)
// ---------------------------------------------------------------------------
extern "C" void kernel_launch(void* const* d_in, const int* in_sizes, int n_in,
                              void* d_out, int out_size) {
    const float* right_embed = (const float*)d_in[0];
    const float* W1          = (const float*)d_in[1];
    const float* Wr          = (const float*)d_in[2];
    const float* br          = (const float*)d_in[3];
    const float* edge_vals   = (const float*)d_in[4];
    const int*   edge_rows   = (const int*)d_in[5];
    const int*   edge_cols   = (const int*)d_in[6];
    const int*   perm        = (const int*)d_in[7];

    const int E = in_sizes[4];
    const int N = in_sizes[7];
    float* out = (float*)d_out;

    cudaFuncSetAttribute(gemm_h, cudaFuncAttributeMaxDynamicSharedMemorySize, SMEM_BYTES);
    cudaFuncSetAttribute(gemm_gate, cudaFuncAttributeMaxDynamicSharedMemorySize, SMEM_BYTES);

    // 0. fp16 conversions
    {
        int n4 = N * (DIM / 4);
        convert_x<<<(n4 + 255) / 256, 256>>>(right_embed, n4);
        int w2 = 2 * DIM * (DIM / 4);
        convert_w<<<(w2 + 255) / 256, 256>>>(W1, Wr);
    }
    // 1. CSR row pointers (boundary scatter)
    {
        build_rowptr_fast<<<(E + 255) / 256, 256>>>(edge_rows, E, N);
    }
    // 2. H = Xh @ W1h
    {
        dim3 grid(DIM / BN, (N + BM - 1) / BM);
        gemm_h<<<grid, 256, SMEM_BYTES>>>(N);
    }
    // 3. SpMM + ReLU
    {
        spmm_relu<<<(N + 7) / 8, 256>>>(edge_vals, edge_cols, N);
    }
    // 4. gate blend
    {
        dim3 grid(DIM / BN, (N + BM - 1) / BM);
        gemm_gate<<<grid, 256, SMEM_BYTES>>>(br, perm, out, N);
    }
}